// round 14
// baseline (speedup 1.0000x reference)
#include <cuda_runtime.h>
#include <cuda_bf16.h>
#include <math.h>

// PyramidROIAlign: B=2, N=1000, C=256, pool 7x7, levels 2..5.
// Output (B,N,7,7,C) float32.
//
// One block per ROI, 512 thr = 16 warps. Warp pair (w>>1) owns pixels
// p = (w>>1)+8k; bit w&1 picks the 512B channel half. All global
// accesses are 64-bit (float2), each fully coalesced over one
// contiguous 256B segment (lane addr = base + lane*8). This halves the
// wavefronts-per-instruction (2 vs 4) to dodge the within-LDG replay
// rate (~2.07 cyc/wf) that pinned L1 at ~50%, and doubles the number
// of independent loads in flight per warp (8 LDG.64).

#define POOLP 7
#define NPIX  (POOLP * POOLP)   // 49

__global__ __launch_bounds__(512, 3)
void pyramid_roi_align_kernel(const float* __restrict__ boxes,
                              const float* __restrict__ meta,
                              const float* __restrict__ f2,
                              const float* __restrict__ f3,
                              const float* __restrict__ f4,
                              const float* __restrict__ f5,
                              float* __restrict__ out,
                              int B, int N)
{
    const int roi = blockIdx.x;            // 0 .. B*N-1
    const int b   = roi / N;

    // ---- per-ROI scalars (warp-uniform, cheap) ----
    const float y1 = boxes[roi * 4 + 0];
    const float x1 = boxes[roi * 4 + 1];
    const float y2 = boxes[roi * 4 + 2];
    const float x2 = boxes[roi * 4 + 3];
    const float h  = y2 - y1;
    const float w  = x2 - x1;

    const float image_area = meta[4] * meta[5];          // image_meta[0,4]*[0,5]
    const float lvl = log2f(sqrtf(h * w) / (224.0f / sqrtf(image_area)));
    float rl = 4.0f + rintf(lvl);                        // jnp.round == rint
    rl = fminf(fmaxf(rl, 2.0f), 5.0f);
    const int level = (int)rl;

    const float* fm;
    int H;
    switch (level) {
        case 2:  fm = f2; H = 256; break;
        case 3:  fm = f3; H = 128; break;
        case 4:  fm = f4; H = 64;  break;
        default: fm = f5; H = 32;  break;
    }
    const int W  = H;
    const int C2 = 128;                                  // 256 ch / 2 (float2 units)

    const float2* __restrict__ fb =
        (const float2*)fm + (size_t)b * H * W * C2;
    float2* __restrict__ o2 =
        (float2*)out + (size_t)roi * NPIX * C2;

    const float Hm1 = (float)(H - 1);
    const float Wm1 = (float)(W - 1);
    const float sy  = h * Hm1 * (1.0f / (POOLP - 1));    // (y2-y1)*(H-1)/(ph-1)
    const float sx  = w * Wm1 * (1.0f / (POOLP - 1));
    const float by  = y1 * Hm1;
    const float bx  = x1 * Wm1;

    const int lane = threadIdx.x & 31;
    const int wrp  = threadIdx.x >> 5;                   // 0..15
    // channel-half h = wrp&1 covers float2 indices [64h, 64h+64) of the row.
    const int e0   = ((wrp & 1) << 6) + lane;            // float2 idx, segment 0
    const int e1   = e0 + 32;                            // float2 idx, segment 1
    const int p0   = wrp >> 1;                           // pixel start 0..7

    for (int p = p0; p < NPIX; p += 8) {
        const int iy = p / POOLP;                        // const-div -> mul
        const int ix = p - iy * POOLP;

        // ---- sample coordinates (exact reference semantics) ----
        const float ys  = by + (float)iy * sy;
        const float xs  = bx + (float)ix * sx;
        const float y0f = floorf(ys);
        const float x0f = floorf(xs);
        int y0 = (int)y0f;  y0 = min(max(y0, 0), H - 1);
        int x0 = (int)x0f;  x0 = min(max(x0, 0), W - 1);
        const int y1i = min(y0 + 1, H - 1);
        const int x1i = min(x0 + 1, W - 1);
        const float fy = ys - y0f;                       // frac from UNclipped floor
        const float fx = xs - x0f;

        // warp-uniform corner base offsets (in float2 units)
        const int off_tl = (y0  * W + x0 ) * C2;
        const int off_tr = (y0  * W + x1i) * C2;
        const int off_bl = (y1i * W + x0 ) * C2;
        const int off_br = (y1i * W + x1i) * C2;

        // 8 independent, fully-coalesced LDG.64 (each = one 256B segment)
        const float2 tl0 = fb[off_tl + e0];
        const float2 tr0 = fb[off_tr + e0];
        const float2 bl0 = fb[off_bl + e0];
        const float2 br0 = fb[off_br + e0];
        const float2 tl1 = fb[off_tl + e1];
        const float2 tr1 = fb[off_tr + e1];
        const float2 bl1 = fb[off_bl + e1];
        const float2 br1 = fb[off_br + e1];

        float2 r0, r1;
        {
            float t, bo;
            t = tl0.x + (tr0.x - tl0.x) * fx;  bo = bl0.x + (br0.x - bl0.x) * fx;  r0.x = t + (bo - t) * fy;
            t = tl0.y + (tr0.y - tl0.y) * fx;  bo = bl0.y + (br0.y - bl0.y) * fx;  r0.y = t + (bo - t) * fy;
            t = tl1.x + (tr1.x - tl1.x) * fx;  bo = bl1.x + (br1.x - bl1.x) * fx;  r1.x = t + (bo - t) * fy;
            t = tl1.y + (tr1.y - tl1.y) * fx;  bo = bl1.y + (br1.y - bl1.y) * fx;  r1.y = t + (bo - t) * fy;
        }
        o2[p * C2 + e0] = r0;
        o2[p * C2 + e1] = r1;
    }
}

extern "C" void kernel_launch(void* const* d_in, const int* in_sizes, int n_in,
                              void* d_out, int out_size)
{
    const float* boxes = (const float*)d_in[0];
    const float* meta  = (const float*)d_in[1];
    const float* f2    = (const float*)d_in[2];
    const float* f3    = (const float*)d_in[3];
    const float* f4    = (const float*)d_in[4];
    const float* f5    = (const float*)d_in[5];
    float* out = (float*)d_out;

    const int B = in_sizes[1] / 14;            // image_meta is (B,14)
    const int N = in_sizes[0] / (4 * B);       // boxes is (B,N,4)

    pyramid_roi_align_kernel<<<B * N, 512>>>(boxes, meta, f2, f3, f4, f5,
                                             out, B, N);
}